// round 3
// baseline (speedup 1.0000x reference)
#include <cuda_runtime.h>
#include <cstdint>

#define T_STEPS 336
#define BATCH   4096
#define NFEAT   32
#define UN1     64
#define UN2     32
#define G1      256   // 4*UN1
#define G2      128   // 4*UN2
#define ROWS    32
#define THREADS 512
#define CTAS    (BATCH / ROWS)   // 128

// ---- shared memory layout (float offsets) ----
#define OFF_W1  0
#define OFF_U1  (OFF_W1 + NFEAT * G1)        // 8192
#define OFF_W2  (OFF_U1 + UN1 * G1)          // 24576
#define OFF_U2  (OFF_W2 + UN1 * G2)          // 32768
#define OFF_B1  (OFF_U2 + UN2 * G2)          // 36864
#define OFF_B2  (OFF_B1 + G1)                // 37120
#define OFF_H1  (OFF_B2 + G2)                // 37248: 2 buffers x 32*64
#define OFF_H2  (OFF_H1 + 2 * ROWS * UN1)    // 41344: 2 buffers x 32*32
#define OFF_X   (OFF_H2 + 2 * ROWS * UN2)    // 43392: 2 buffers x 32*32
#define SMEM_FLOATS (OFF_X + 2 * ROWS * NFEAT) // 45440 -> 181760 bytes

typedef unsigned long long ull;

// ---------------- packed f32x2 helpers ----------------
__device__ __forceinline__ ull pack2(float a) {
    ull r;
    asm("mov.b64 %0, {%1, %1};" : "=l"(r) : "f"(a));
    return r;
}
__device__ __forceinline__ ull fma2(ull a, ull b, ull c) {
    ull d;
    asm("fma.rn.f32x2 %0, %1, %2, %3;" : "=l"(d) : "l"(a), "l"(b), "l"(c));
    return d;
}
__device__ __forceinline__ float2 unpack2(ull v) {
    float2 r;
    asm("mov.b64 {%0, %1}, %2;" : "=f"(r.x), "=f"(r.y) : "l"(v));
    return r;
}

// ---------------- activations (fast HW exp/rcp, ~1e-6 err) ----------------
__device__ __forceinline__ float sigm(float x) {
    float e = __expf(-x);
    return __fdividef(1.0f, 1.0f + e);
}
__device__ __forceinline__ float tanh_(float x) {
    float ax = fabsf(x);
    float e  = __expf(-2.0f * ax);          // in (0,1], no overflow
    float r  = __fdividef(1.0f - e, 1.0f + e);
    return copysignf(r, x);
}

// ---------------- cp.async helpers ----------------
__device__ __forceinline__ void cp16(uint32_t saddr, const float* g) {
    asm volatile("cp.async.cg.shared.global [%0], [%1], 16;" :: "r"(saddr), "l"(g));
}
__device__ __forceinline__ void cp_commit() {
    asm volatile("cp.async.commit_group;");
}
__device__ __forceinline__ void cp_wait0() {
    asm volatile("cp.async.wait_group 0;" ::: "memory");
}

// R-row tile: one k-slice, R row broadcasts x (2 units x 4 gates)
template <int R, int GS>
__device__ __forceinline__ void mmaR(ull (&acc)[R][4], const float (&h)[R],
                                     const float* __restrict__ wr) {
    ull w0 = *(const ull*)(wr);
    ull w1 = *(const ull*)(wr + GS);
    ull w2 = *(const ull*)(wr + 2 * GS);
    ull w3 = *(const ull*)(wr + 3 * GS);
#pragma unroll
    for (int r = 0; r < R; r++) {
        ull p = pack2(h[r]);
        acc[r][0] = fma2(p, w0, acc[r][0]);
        acc[r][1] = fma2(p, w1, acc[r][1]);
        acc[r][2] = fma2(p, w2, acc[r][2]);
        acc[r][3] = fma2(p, w3, acc[r][3]);
    }
}

// K-panel GEMM: R rows x (2 units x 4 gates), K columns, input stride IS,
// gate stride GS, weight row stride GS*4... (weights at wbase + k*WS + 2*up)
template <int R, int K, int IS, int WS, int GS>
__device__ __forceinline__ void panel(ull (&acc)[R][4],
                                      const float* __restrict__ in,
                                      const float* __restrict__ wbase) {
#pragma unroll 1
    for (int k = 0; k < K; k += 4) {
        float4 a[R];
#pragma unroll
        for (int r = 0; r < R; r++) a[r] = *(const float4*)(in + r * IS + k);
        const float* w = wbase + k * WS;
        float hh[R];
#pragma unroll
        for (int r = 0; r < R; r++) hh[r] = a[r].x;
        mmaR<R, GS>(acc, hh, w);
#pragma unroll
        for (int r = 0; r < R; r++) hh[r] = a[r].y;
        mmaR<R, GS>(acc, hh, w + WS);
#pragma unroll
        for (int r = 0; r < R; r++) hh[r] = a[r].z;
        mmaR<R, GS>(acc, hh, w + 2 * WS);
#pragma unroll
        for (int r = 0; r < R; r++) hh[r] = a[r].w;
        mmaR<R, GS>(acc, hh, w + 3 * WS);
    }
}

__global__ void __launch_bounds__(THREADS, 1)
lstm_fused_kernel(const float* __restrict__ x,
                  const float* __restrict__ W1, const float* __restrict__ U1w, const float* __restrict__ b1,
                  const float* __restrict__ W2, const float* __restrict__ U2w, const float* __restrict__ b2,
                  const float* __restrict__ Wv, const float* __restrict__ bv,
                  const float* __restrict__ Wo, const float* __restrict__ bo,
                  const float* __restrict__ Wd1, const float* __restrict__ bd1,
                  const float* __restrict__ Wd2, const float* __restrict__ bd2,
                  float* __restrict__ out) {
    extern __shared__ float sm[];
    const int tid = threadIdx.x;
    const int b0  = blockIdx.x * ROWS;

    // ---- stage weights into SMEM (one time) ----
    for (int i = tid; i < (NFEAT * G1) / 4; i += THREADS)
        ((float4*)(sm + OFF_W1))[i] = ((const float4*)W1)[i];
    for (int i = tid; i < (UN1 * G1) / 4; i += THREADS)
        ((float4*)(sm + OFF_U1))[i] = ((const float4*)U1w)[i];
    for (int i = tid; i < (UN1 * G2) / 4; i += THREADS)
        ((float4*)(sm + OFF_W2))[i] = ((const float4*)W2)[i];
    for (int i = tid; i < (UN2 * G2) / 4; i += THREADS)
        ((float4*)(sm + OFF_U2))[i] = ((const float4*)U2w)[i];
    for (int i = tid; i < G1; i += THREADS) sm[OFF_B1 + i] = b1[i];
    for (int i = tid; i < G2; i += THREADS) sm[OFF_B2 + i] = b2[i];
    for (int i = tid; i < 2 * ROWS * UN1; i += THREADS) sm[OFF_H1 + i] = 0.0f;
    for (int i = tid; i < 2 * ROWS * UN2; i += THREADS) sm[OFF_H2 + i] = 0.0f;

    // warps 0-7: layer 1 (4-row tiles).  warps 8-15: layer 2 (2-row tiles), one step behind.
    const bool isL1 = (tid < 256);
    const int up  = tid & 31;          // L1 unit pair (0..31)
    const int rg  = (tid >> 5) & 7;    // L1 row group (4 rows)
    const int lt  = tid & 255;
    const int up2 = lt & 15;           // L2 unit pair (0..15)
    const int rg2 = lt >> 4;           // L2 row group (2 rows), 0..15

    float c1[4][2];
    float c2[2][2];
#pragma unroll
    for (int r = 0; r < 4; r++) { c1[r][0] = c1[r][1] = 0.0f; }
#pragma unroll
    for (int r = 0; r < 2; r++) { c2[r][0] = c2[r][1] = 0.0f; }

    // ---- x prefetch mapping: threads 0-255 move one float4 per step ----
    const int xrow = tid >> 3;   // 0..31 (for tid<256)
    const int xq   = tid & 7;    // 0..7
    const float* xg = x + ((size_t)(b0 + xrow) * T_STEPS) * NFEAT + xq * 4;
    uint32_t sx0 = (uint32_t)__cvta_generic_to_shared(sm + OFF_X + xrow * NFEAT + xq * 4);
    const uint32_t xbufstride = ROWS * NFEAT * 4;   // bytes
    const bool xmover = (tid < 256);

    if (xmover) { cp16(sx0, xg); }    // prefetch x_0 into buffer 0
    cp_commit();

    __syncthreads();   // weights + zero state visible

    // Iter t: L1 computes step t (t<T), L2 computes step t-1 (t>=1).
    for (int t = 0; t <= T_STEPS; ++t) {
        if (t < T_STEPS) cp_wait0();   // x_t landed
        __syncthreads();               // single barrier per step
        if (t + 1 < T_STEPS && xmover) {
            cp16(sx0 + ((t + 1) & 1) * xbufstride, xg + (size_t)(t + 1) * NFEAT);
        }
        cp_commit();
        const int rb = t & 1, wb = rb ^ 1;
        const float* h1r = sm + OFF_H1 + rb * (ROWS * UN1);
        float*       h1w = sm + OFF_H1 + wb * (ROWS * UN1);
        const float* h2r = sm + OFF_H2 + rb * (ROWS * UN2);
        float*       h2w = sm + OFF_H2 + wb * (ROWS * UN2);
        const float* xb  = sm + OFF_X + rb * (ROWS * NFEAT);

        if (isL1) {
            if (t < T_STEPS) {
                ull acc[4][4];
#pragma unroll
                for (int g = 0; g < 4; g++) {
                    ull bsv = *(const ull*)(sm + OFF_B1 + g * UN1 + 2 * up);
#pragma unroll
                    for (int r = 0; r < 4; r++) acc[r][g] = bsv;
                }
                panel<4, NFEAT, NFEAT, G1, UN1>(acc, xb + rg * 4 * NFEAT,
                                                sm + OFF_W1 + 2 * up);
                panel<4, UN1, UN1, G1, UN1>(acc, h1r + rg * 4 * UN1,
                                            sm + OFF_U1 + 2 * up);
                // activations + state update (Keras gate order i,f,c,o)
#pragma unroll
                for (int r = 0; r < 4; r++) {
                    float2 zi = unpack2(acc[r][0]);
                    float2 zf = unpack2(acc[r][1]);
                    float2 zg = unpack2(acc[r][2]);
                    float2 zo = unpack2(acc[r][3]);
                    float i0 = sigm(zi.x), f0 = sigm(zf.x), g0 = tanh_(zg.x), o0 = sigm(zo.x);
                    float i1 = sigm(zi.y), f1 = sigm(zf.y), g1 = tanh_(zg.y), o1 = sigm(zo.y);
                    c1[r][0] = f0 * c1[r][0] + i0 * g0;
                    c1[r][1] = f1 * c1[r][1] + i1 * g1;
                    float2 h;
                    h.x = o0 * tanh_(c1[r][0]);
                    h.y = o1 * tanh_(c1[r][1]);
                    *(float2*)(h1w + (rg * 4 + r) * UN1 + 2 * up) = h;
                }
            }
        } else {
            if (t >= 1) {
                ull acc2[2][4];
#pragma unroll
                for (int g = 0; g < 4; g++) {
                    ull bsv = *(const ull*)(sm + OFF_B2 + g * UN2 + 2 * up2);
#pragma unroll
                    for (int r = 0; r < 2; r++) acc2[r][g] = bsv;
                }
                panel<2, UN1, UN1, G2, UN2>(acc2, h1r + rg2 * 2 * UN1,
                                            sm + OFF_W2 + 2 * up2);
                panel<2, UN2, UN2, G2, UN2>(acc2, h2r + rg2 * 2 * UN2,
                                            sm + OFF_U2 + 2 * up2);
#pragma unroll
                for (int r = 0; r < 2; r++) {
                    float2 zi = unpack2(acc2[r][0]);
                    float2 zf = unpack2(acc2[r][1]);
                    float2 zg = unpack2(acc2[r][2]);
                    float2 zo = unpack2(acc2[r][3]);
                    float i0 = sigm(zi.x), f0 = sigm(zf.x), g0 = tanh_(zg.x), o0 = sigm(zo.x);
                    float i1 = sigm(zi.y), f1 = sigm(zf.y), g1 = tanh_(zg.y), o1 = sigm(zo.y);
                    c2[r][0] = f0 * c2[r][0] + i0 * g0;
                    c2[r][1] = f1 * c2[r][1] + i1 * g1;
                    float2 h;
                    h.x = o0 * tanh_(c2[r][0]);
                    h.y = o1 * tanh_(c2[r][1]);
                    *(float2*)(h2w + (rg2 * 2 + r) * UN2 + 2 * up2) = h;
                }
            }
        }
    }
    __syncthreads();

    // final h2 = h2_{T-1}, written at iter t=T into buf ((T&1)^1)
    const float* h2f = sm + OFF_H2 + ((T_STEPS & 1) ^ 1) * (ROWS * UN2);

    // ================= head: MHA(seq=1) is identity-attention -> v@Wo, then MLP =================
    float* sv = sm + OFF_X;             // 32x32 scratch
    for (int idx = tid; idx < ROWS * 32; idx += THREADS) {
        int r = idx >> 5, j = idx & 31;
        float s = bv[j];
        const float* h2row = h2f + r * UN2;
#pragma unroll
        for (int d = 0; d < 32; d++) s += h2row[d] * Wv[d * 32 + j];
        sv[idx] = s;
    }
    __syncthreads();
    float* so = sm + OFF_H1;            // 32x32 scratch
    for (int idx = tid; idx < ROWS * 32; idx += THREADS) {
        int r = idx >> 5, e = idx & 31;
        float s = bo[e];
#pragma unroll
        for (int j = 0; j < 32; j++) s += sv[r * 32 + j] * Wo[j * 32 + e];
        so[idx] = s;
    }
    __syncthreads();
    float* sd1 = sm + OFF_X;            // 32x64 scratch
    for (int idx = tid; idx < ROWS * 64; idx += THREADS) {
        int r = idx >> 6, m = idx & 63;
        float s = bd1[m];
#pragma unroll
        for (int e = 0; e < 32; e++) s += so[r * 32 + e] * Wd1[e * 64 + m];
        sd1[idx] = fmaxf(s, 0.0f);
    }
    __syncthreads();
    for (int idx = tid; idx < ROWS * 24; idx += THREADS) {
        int r = idx / 24, p = idx % 24;
        float s = bd2[p];
#pragma unroll
        for (int m = 0; m < 64; m++) s += sd1[r * 64 + m] * Wd2[m * 24 + p];
        out[(size_t)(b0 + r) * 24 + p] = s;
    }
}

extern "C" void kernel_launch(void* const* d_in, const int* in_sizes, int n_in,
                              void* d_out, int out_size) {
    const float* x   = (const float*)d_in[0];
    const float* W1  = (const float*)d_in[1];
    const float* U1w = (const float*)d_in[2];
    const float* b1  = (const float*)d_in[3];
    const float* W2  = (const float*)d_in[4];
    const float* U2w = (const float*)d_in[5];
    const float* b2  = (const float*)d_in[6];
    // d_in[7..10] = Wq, bq, Wk, bk: dead (softmax over seq-len 1 == 1)
    const float* Wv  = (const float*)d_in[11];
    const float* bv  = (const float*)d_in[12];
    const float* Wo  = (const float*)d_in[13];
    const float* bo  = (const float*)d_in[14];
    const float* Wd1 = (const float*)d_in[15];
    const float* bd1 = (const float*)d_in[16];
    const float* Wd2 = (const float*)d_in[17];
    const float* bd2 = (const float*)d_in[18];

    size_t smem = SMEM_FLOATS * sizeof(float);   // 181760 B
    cudaFuncSetAttribute(lstm_fused_kernel,
                         cudaFuncAttributeMaxDynamicSharedMemorySize, (int)smem);
    lstm_fused_kernel<<<CTAS, THREADS, smem>>>(
        x, W1, U1w, b1, W2, U2w, b2, Wv, bv, Wo, bo, Wd1, bd1, Wd2, bd2,
        (float*)d_out);
}

// round 4
// speedup vs baseline: 1.0991x; 1.0991x over previous
#include <cuda_runtime.h>
#include <cstdint>

#define T_STEPS 336
#define BATCH   4096
#define NFEAT   32
#define UN1     64
#define UN2     32
#define G1      256   // 4*UN1
#define G2      128   // 4*UN2
#define ROWS    32
#define THREADS 512
#define CTAS    (BATCH / ROWS)   // 128
#define RSTRIDE 128   // combined input row stride: [x(32)|h1(64)|h2(32)]

// ---- shared memory layout (float offsets) ----
#define OFF_W1  0                              // stacked [W1;U1]: 96 x 256
#define OFF_W2  (OFF_W1 + 96 * G1)             // 24576: stacked [W2;U2]: 96 x 128
#define OFF_B1  (OFF_W2 + 96 * G2)             // 36864
#define OFF_B2  (OFF_B1 + G1)                  // 37120
#define OFF_C   (OFF_B2 + G2)                  // 37248: 2 buffers x 32 x 128
#define SMEM_FLOATS (OFF_C + 2 * ROWS * RSTRIDE) // 45440 -> 181760 bytes

typedef unsigned long long ull;

// ---------------- packed f32x2 helpers ----------------
__device__ __forceinline__ ull pack2(float a) {
    ull r; asm("mov.b64 %0, {%1, %1};" : "=l"(r) : "f"(a)); return r;
}
__device__ __forceinline__ ull fma2(ull a, ull b, ull c) {
    ull d; asm("fma.rn.f32x2 %0, %1, %2, %3;" : "=l"(d) : "l"(a), "l"(b), "l"(c)); return d;
}
__device__ __forceinline__ ull add2(ull a, ull b) {
    ull d; asm("add.rn.f32x2 %0, %1, %2;" : "=l"(d) : "l"(a), "l"(b)); return d;
}
__device__ __forceinline__ float2 unpack2(ull v) {
    float2 r; asm("mov.b64 {%0, %1}, %2;" : "=f"(r.x), "=f"(r.y) : "l"(v)); return r;
}

// ---------------- activations (fast HW exp/rcp, ~1e-6 err) ----------------
__device__ __forceinline__ float sigm(float x) {
    float e = __expf(-x);
    return __fdividef(1.0f, 1.0f + e);
}
__device__ __forceinline__ float tanh_(float x) {
    float ax = fabsf(x);
    float e  = __expf(-2.0f * ax);
    float r  = __fdividef(1.0f - e, 1.0f + e);
    return copysignf(r, x);
}

// ---------------- cp.async helpers ----------------
__device__ __forceinline__ void cp16(uint32_t saddr, const float* g) {
    asm volatile("cp.async.cg.shared.global [%0], [%1], 16;" :: "r"(saddr), "l"(g));
}
__device__ __forceinline__ void cp_commit() { asm volatile("cp.async.commit_group;"); }
__device__ __forceinline__ void cp_wait0()  { asm volatile("cp.async.wait_group 0;" ::: "memory"); }

// R-row k-slice: R row broadcasts x (2 units x 4 gates)
template <int R, int GS>
__device__ __forceinline__ void mmaR(ull (&acc)[R][4], const float (&h)[R],
                                     const float* __restrict__ wr) {
    ull w0 = *(const ull*)(wr);
    ull w1 = *(const ull*)(wr + GS);
    ull w2 = *(const ull*)(wr + 2 * GS);
    ull w3 = *(const ull*)(wr + 3 * GS);
#pragma unroll
    for (int r = 0; r < R; r++) {
        ull p = pack2(h[r]);
        acc[r][0] = fma2(p, w0, acc[r][0]);
        acc[r][1] = fma2(p, w1, acc[r][1]);
        acc[r][2] = fma2(p, w2, acc[r][2]);
        acc[r][3] = fma2(p, w3, acc[r][3]);
    }
}

// Uniform 48-column panel: R rows, input at 'in' (row stride RSTRIDE),
// weights at 'wb' (row stride WS, gate stride GS).
template <int R, int WS, int GS>
__device__ __forceinline__ void panel48(ull (&acc)[R][4],
                                        const float* __restrict__ in,
                                        const float* __restrict__ wb) {
#pragma unroll 2
    for (int k = 0; k < 48; k += 2) {
        float2 a[R];
#pragma unroll
        for (int r = 0; r < R; r++) a[r] = *(const float2*)(in + r * RSTRIDE + k);
        const float* w = wb + k * WS;
        float hh[R];
#pragma unroll
        for (int r = 0; r < R; r++) hh[r] = a[r].x;
        mmaR<R, GS>(acc, hh, w);
#pragma unroll
        for (int r = 0; r < R; r++) hh[r] = a[r].y;
        mmaR<R, GS>(acc, hh, w + WS);
    }
}

__global__ void __launch_bounds__(THREADS, 1)
lstm_fused_kernel(const float* __restrict__ x,
                  const float* __restrict__ W1, const float* __restrict__ U1w, const float* __restrict__ b1,
                  const float* __restrict__ W2, const float* __restrict__ U2w, const float* __restrict__ b2,
                  const float* __restrict__ Wv, const float* __restrict__ bv,
                  const float* __restrict__ Wo, const float* __restrict__ bo,
                  const float* __restrict__ Wd1, const float* __restrict__ bd1,
                  const float* __restrict__ Wd2, const float* __restrict__ bd2,
                  float* __restrict__ out) {
    extern __shared__ float sm[];
    const int tid = threadIdx.x;
    const int b0  = blockIdx.x * ROWS;

    // ---- stage stacked weights into SMEM (one time) ----
    // [W1;U1]: W1 is 32x256, U1 is 64x256, contiguous rows 0..95
    for (int i = tid; i < (NFEAT * G1) / 4; i += THREADS)
        ((float4*)(sm + OFF_W1))[i] = ((const float4*)W1)[i];
    for (int i = tid; i < (UN1 * G1) / 4; i += THREADS)
        ((float4*)(sm + OFF_W1 + NFEAT * G1))[i] = ((const float4*)U1w)[i];
    // [W2;U2]: W2 is 64x128, U2 is 32x128
    for (int i = tid; i < (UN1 * G2) / 4; i += THREADS)
        ((float4*)(sm + OFF_W2))[i] = ((const float4*)W2)[i];
    for (int i = tid; i < (UN2 * G2) / 4; i += THREADS)
        ((float4*)(sm + OFF_W2 + UN1 * G2))[i] = ((const float4*)U2w)[i];
    for (int i = tid; i < G1; i += THREADS) sm[OFF_B1 + i] = b1[i];
    for (int i = tid; i < G2; i += THREADS) sm[OFF_B2 + i] = b2[i];
    // zero both combined buffers
    for (int i = tid; i < 2 * ROWS * RSTRIDE; i += THREADS) sm[OFF_C + i] = 0.0f;

    __syncthreads();   // zeroing done before cp.async writes x

    // ---- thread mapping ----
    // warps 0-7: layer 1. 8-row tiles, K-split x2 across lane bit 4.
    // warps 8-15: layer 2. 4-row tiles, K-split x2, one step behind.
    const bool isL1 = (tid < 256);
    const int wg = (tid & 255) >> 5;   // 0..7 within layer group
    const int l  = tid & 31;
    const int kh = l >> 4;             // K-half (0/1)
    // L1: row base rg*8, unit pair up (0..31)
    const int rg = wg & 3;
    const int up = (l & 15) | ((wg >> 2) << 4);
    // L2: row base rg2*4, unit pair up2 (0..15)
    const int rg2 = wg;
    const int up2 = l & 15;

    float c1[4][2];   // L1: this thread's 4 activation rows (kh-half of 8)
    float c2[2][2];   // L2: 2 activation rows
#pragma unroll
    for (int r = 0; r < 4; r++) { c1[r][0] = c1[r][1] = 0.0f; }
#pragma unroll
    for (int r = 0; r < 2; r++) { c2[r][0] = c2[r][1] = 0.0f; }

    // ---- x prefetch: threads 0-255 move one float4/step into combined rows ----
    const int xrow = tid >> 3;   // 0..31 (valid for tid<256)
    const int xq   = tid & 7;
    const float* xg = x + ((size_t)(b0 + xrow) * T_STEPS) * NFEAT + xq * 4;
    uint32_t sx0 = (uint32_t)__cvta_generic_to_shared(sm + OFF_C + xrow * RSTRIDE + xq * 4);
    const uint32_t cbufbytes = ROWS * RSTRIDE * 4;   // 16384
    const bool xmover = (tid < 256);

    if (xmover) cp16(sx0, xg);    // x_0 -> buffer 0
    cp_commit();
    __syncthreads();

    // Iter t: L1 computes step t (t<T) reading buf rb=t&1, writing h1_t to wb.
    //         L2 computes step t-1 (t>=1) reading buf rb, writing h2_{t-1} to wb.
    for (int t = 0; t <= T_STEPS; ++t) {
        if (t < T_STEPS) cp_wait0();
        __syncthreads();
        if (t + 1 < T_STEPS && xmover)
            cp16(sx0 + ((t + 1) & 1) * cbufbytes, xg + (size_t)(t + 1) * NFEAT);
        cp_commit();
        const int rb = t & 1, wb = rb ^ 1;
        const float* cin  = sm + OFF_C + rb * (ROWS * RSTRIDE);
        float*       cout = sm + OFF_C + wb * (ROWS * RSTRIDE);

        if (isL1) {
            if (t < T_STEPS) {
                ull acc[8][4];
#pragma unroll
                for (int g = 0; g < 4; g++) {
                    ull bsv = (kh == 0) ? *(const ull*)(sm + OFF_B1 + g * UN1 + 2 * up) : 0ull;
#pragma unroll
                    for (int r = 0; r < 8; r++) acc[r][g] = bsv;
                }
                // gate cols = [x|h1] = cin cols 0..95; this thread: cols kh*48..+48
                panel48<8, G1, UN1>(acc,
                                    cin + rg * 8 * RSTRIDE + kh * 48,
                                    sm + OFF_W1 + (kh * 48) * G1 + 2 * up);
                // K-split reduction with partner lane (l ^ 16)
#pragma unroll
                for (int r = 0; r < 8; r++)
#pragma unroll
                    for (int g = 0; g < 4; g++)
                        acc[r][g] = add2(acc[r][g], __shfl_xor_sync(0xffffffffu, acc[r][g], 16));
                // activations: kh=0 -> rows 0..3, kh=1 -> rows 4..7 of the tile
#pragma unroll
                for (int r = 0; r < 4; r++) {
                    float2 zi = unpack2(kh ? acc[r + 4][0] : acc[r][0]);
                    float2 zf = unpack2(kh ? acc[r + 4][1] : acc[r][1]);
                    float2 zg = unpack2(kh ? acc[r + 4][2] : acc[r][2]);
                    float2 zo = unpack2(kh ? acc[r + 4][3] : acc[r][3]);
                    float i0 = sigm(zi.x), f0 = sigm(zf.x), g0 = tanh_(zg.x), o0 = sigm(zo.x);
                    float i1 = sigm(zi.y), f1 = sigm(zf.y), g1 = tanh_(zg.y), o1 = sigm(zo.y);
                    c1[r][0] = f0 * c1[r][0] + i0 * g0;
                    c1[r][1] = f1 * c1[r][1] + i1 * g1;
                    float2 h;
                    h.x = o0 * tanh_(c1[r][0]);
                    h.y = o1 * tanh_(c1[r][1]);
                    int row = rg * 8 + kh * 4 + r;
                    *(float2*)(cout + row * RSTRIDE + 32 + 2 * up) = h;
                }
            }
        } else {
            if (t >= 1) {
                ull acc2[4][4];
#pragma unroll
                for (int g = 0; g < 4; g++) {
                    ull bsv = (kh == 0) ? *(const ull*)(sm + OFF_B2 + g * UN2 + 2 * up2) : 0ull;
#pragma unroll
                    for (int r = 0; r < 4; r++) acc2[r][g] = bsv;
                }
                // gate cols = [h1|h2] = cin cols 32..127; this thread: cols 32+kh*48..+48
                panel48<4, G2, UN2>(acc2,
                                    cin + rg2 * 4 * RSTRIDE + 32 + kh * 48,
                                    sm + OFF_W2 + (kh * 48) * G2 + 2 * up2);
#pragma unroll
                for (int r = 0; r < 4; r++)
#pragma unroll
                    for (int g = 0; g < 4; g++)
                        acc2[r][g] = add2(acc2[r][g], __shfl_xor_sync(0xffffffffu, acc2[r][g], 16));
#pragma unroll
                for (int r = 0; r < 2; r++) {
                    float2 zi = unpack2(kh ? acc2[r + 2][0] : acc2[r][0]);
                    float2 zf = unpack2(kh ? acc2[r + 2][1] : acc2[r][1]);
                    float2 zg = unpack2(kh ? acc2[r + 2][2] : acc2[r][2]);
                    float2 zo = unpack2(kh ? acc2[r + 2][3] : acc2[r][3]);
                    float i0 = sigm(zi.x), f0 = sigm(zf.x), g0 = tanh_(zg.x), o0 = sigm(zo.x);
                    float i1 = sigm(zi.y), f1 = sigm(zf.y), g1 = tanh_(zg.y), o1 = sigm(zo.y);
                    c2[r][0] = f0 * c2[r][0] + i0 * g0;
                    c2[r][1] = f1 * c2[r][1] + i1 * g1;
                    float2 h;
                    h.x = o0 * tanh_(c2[r][0]);
                    h.y = o1 * tanh_(c2[r][1]);
                    int row = rg2 * 4 + kh * 2 + r;
                    *(float2*)(cout + row * RSTRIDE + 96 + 2 * up2) = h;
                }
            }
        }
    }
    __syncthreads();

    // final h2 = h2_{T-1}, written at iter t=T into buf ((T&1)^1), cols 96..127
    const float* h2f = sm + OFF_C + ((T_STEPS & 1) ^ 1) * (ROWS * RSTRIDE) + 96;

    // ================= head: MHA(seq=1) is identity-attention -> v@Wo, then MLP ===========
    // scratch lives in the (now dead) weight region
    float* sv  = sm + OFF_W1;            // 32x32
    float* so  = sm + OFF_W1 + 1024;     // 32x32
    float* sd1 = sm + OFF_W1 + 2048;     // 32x64
    for (int idx = tid; idx < ROWS * 32; idx += THREADS) {
        int r = idx >> 5, j = idx & 31;
        float s = bv[j];
        const float* h2row = h2f + r * RSTRIDE;
#pragma unroll
        for (int d = 0; d < 32; d++) s += h2row[d] * Wv[d * 32 + j];
        sv[idx] = s;
    }
    __syncthreads();
    for (int idx = tid; idx < ROWS * 32; idx += THREADS) {
        int r = idx >> 5, e = idx & 31;
        float s = bo[e];
#pragma unroll
        for (int j = 0; j < 32; j++) s += sv[r * 32 + j] * Wo[j * 32 + e];
        so[idx] = s;
    }
    __syncthreads();
    for (int idx = tid; idx < ROWS * 64; idx += THREADS) {
        int r = idx >> 6, m = idx & 63;
        float s = bd1[m];
#pragma unroll
        for (int e = 0; e < 32; e++) s += so[r * 32 + e] * Wd1[e * 64 + m];
        sd1[idx] = fmaxf(s, 0.0f);
    }
    __syncthreads();
    for (int idx = tid; idx < ROWS * 24; idx += THREADS) {
        int r = idx / 24, p = idx % 24;
        float s = bd2[p];
#pragma unroll
        for (int m = 0; m < 64; m++) s += sd1[r * 64 + m] * Wd2[m * 24 + p];
        out[(size_t)(b0 + r) * 24 + p] = s;
    }
}

extern "C" void kernel_launch(void* const* d_in, const int* in_sizes, int n_in,
                              void* d_out, int out_size) {
    const float* x   = (const float*)d_in[0];
    const float* W1  = (const float*)d_in[1];
    const float* U1w = (const float*)d_in[2];
    const float* b1  = (const float*)d_in[3];
    const float* W2  = (const float*)d_in[4];
    const float* U2w = (const float*)d_in[5];
    const float* b2  = (const float*)d_in[6];
    // d_in[7..10] = Wq, bq, Wk, bk: dead (softmax over seq-len 1 == 1)
    const float* Wv  = (const float*)d_in[11];
    const float* bv  = (const float*)d_in[12];
    const float* Wo  = (const float*)d_in[13];
    const float* bo  = (const float*)d_in[14];
    const float* Wd1 = (const float*)d_in[15];
    const float* bd1 = (const float*)d_in[16];
    const float* Wd2 = (const float*)d_in[17];
    const float* bd2 = (const float*)d_in[18];

    size_t smem = SMEM_FLOATS * sizeof(float);   // 181760 B
    cudaFuncSetAttribute(lstm_fused_kernel,
                         cudaFuncAttributeMaxDynamicSharedMemorySize, (int)smem);
    lstm_fused_kernel<<<CTAS, THREADS, smem>>>(
        x, W1, U1w, b1, W2, U2w, b2, Wv, bv, Wo, bo, Wd1, bd1, Wd2, bd2,
        (float*)d_out);
}

// round 5
// speedup vs baseline: 1.0992x; 1.0001x over previous
#include <cuda_runtime.h>
#include <cstdint>

#define T_STEPS 336
#define BATCH   4096
#define NFEAT   32
#define UN1     64
#define UN2     32
#define G1      256   // 4*UN1
#define G2      128   // 4*UN2
#define ROWS    32
#define THREADS 512
#define CTAS    (BATCH / ROWS)   // 128
#define RSTRIDE 128   // combined input row stride: [x(32)|h1(64)|h2(32)]

// ---- shared memory layout (float offsets) ----
#define OFF_W1  0                              // stacked [W1;U1]: 96 x 256
#define OFF_W2  (OFF_W1 + 96 * G1)             // 24576: stacked [W2;U2]: 96 x 128
#define OFF_B1  (OFF_W2 + 96 * G2)             // 36864
#define OFF_B2  (OFF_B1 + G1)                  // 37120
#define OFF_C   (OFF_B2 + G2)                  // 37248: 2 buffers x 32 x 128
#define SMEM_FLOATS (OFF_C + 2 * ROWS * RSTRIDE) // 45440 -> 181760 bytes

typedef unsigned long long ull;

// ---------------- packed f32x2 helpers ----------------
__device__ __forceinline__ ull pack2(float a) {
    ull r; asm("mov.b64 %0, {%1, %1};" : "=l"(r) : "f"(a)); return r;
}
__device__ __forceinline__ ull fma2(ull a, ull b, ull c) {
    ull d; asm("fma.rn.f32x2 %0, %1, %2, %3;" : "=l"(d) : "l"(a), "l"(b), "l"(c)); return d;
}
__device__ __forceinline__ ull add2(ull a, ull b) {
    ull d; asm("add.rn.f32x2 %0, %1, %2;" : "=l"(d) : "l"(a), "l"(b)); return d;
}
__device__ __forceinline__ float2 unpack2(ull v) {
    float2 r; asm("mov.b64 {%0, %1}, %2;" : "=f"(r.x), "=f"(r.y) : "l"(v)); return r;
}

// ---------------- activations (fast HW exp/rcp, ~1e-6 err) ----------------
__device__ __forceinline__ float sigm(float x) {
    float e = __expf(-x);
    return __fdividef(1.0f, 1.0f + e);
}
__device__ __forceinline__ float tanh_(float x) {
    float ax = fabsf(x);
    float e  = __expf(-2.0f * ax);
    float r  = __fdividef(1.0f - e, 1.0f + e);
    return copysignf(r, x);
}

// ---------------- cp.async helpers ----------------
__device__ __forceinline__ void cp16(uint32_t saddr, const float* g) {
    asm volatile("cp.async.cg.shared.global [%0], [%1], 16;" :: "r"(saddr), "l"(g));
}
__device__ __forceinline__ void cp_commit() { asm volatile("cp.async.commit_group;"); }
__device__ __forceinline__ void cp_wait0()  { asm volatile("cp.async.wait_group 0;" ::: "memory"); }

// R-row k-slice: R row broadcasts x (2 units x 4 gates)
template <int R, int GS>
__device__ __forceinline__ void mmaR(ull (&acc)[R][4], const float (&h)[R],
                                     const float* __restrict__ wr) {
    ull w0 = *(const ull*)(wr);
    ull w1 = *(const ull*)(wr + GS);
    ull w2 = *(const ull*)(wr + 2 * GS);
    ull w3 = *(const ull*)(wr + 3 * GS);
#pragma unroll
    for (int r = 0; r < R; r++) {
        ull p = pack2(h[r]);
        acc[r][0] = fma2(p, w0, acc[r][0]);
        acc[r][1] = fma2(p, w1, acc[r][1]);
        acc[r][2] = fma2(p, w2, acc[r][2]);
        acc[r][3] = fma2(p, w3, acc[r][3]);
    }
}

// Uniform 48-column panel: R rows, input at 'in' (row stride RSTRIDE),
// weights at 'wb' (row stride WS, gate stride GS).
template <int R, int WS, int GS>
__device__ __forceinline__ void panel48(ull (&acc)[R][4],
                                        const float* __restrict__ in,
                                        const float* __restrict__ wb) {
#pragma unroll 2
    for (int k = 0; k < 48; k += 2) {
        float2 a[R];
#pragma unroll
        for (int r = 0; r < R; r++) a[r] = *(const float2*)(in + r * RSTRIDE + k);
        const float* w = wb + k * WS;
        float hh[R];
#pragma unroll
        for (int r = 0; r < R; r++) hh[r] = a[r].x;
        mmaR<R, GS>(acc, hh, w);
#pragma unroll
        for (int r = 0; r < R; r++) hh[r] = a[r].y;
        mmaR<R, GS>(acc, hh, w + WS);
    }
}

__global__ void __launch_bounds__(THREADS, 1)
lstm_fused_kernel(const float* __restrict__ x,
                  const float* __restrict__ W1, const float* __restrict__ U1w, const float* __restrict__ b1,
                  const float* __restrict__ W2, const float* __restrict__ U2w, const float* __restrict__ b2,
                  const float* __restrict__ Wv, const float* __restrict__ bv,
                  const float* __restrict__ Wo, const float* __restrict__ bo,
                  const float* __restrict__ Wd1, const float* __restrict__ bd1,
                  const float* __restrict__ Wd2, const float* __restrict__ bd2,
                  float* __restrict__ out) {
    extern __shared__ float sm[];
    const int tid = threadIdx.x;
    const int b0  = blockIdx.x * ROWS;

    // ---- stage stacked weights into SMEM (one time) ----
    // [W1;U1]: W1 is 32x256, U1 is 64x256, contiguous rows 0..95
    for (int i = tid; i < (NFEAT * G1) / 4; i += THREADS)
        ((float4*)(sm + OFF_W1))[i] = ((const float4*)W1)[i];
    for (int i = tid; i < (UN1 * G1) / 4; i += THREADS)
        ((float4*)(sm + OFF_W1 + NFEAT * G1))[i] = ((const float4*)U1w)[i];
    // [W2;U2]: W2 is 64x128, U2 is 32x128
    for (int i = tid; i < (UN1 * G2) / 4; i += THREADS)
        ((float4*)(sm + OFF_W2))[i] = ((const float4*)W2)[i];
    for (int i = tid; i < (UN2 * G2) / 4; i += THREADS)
        ((float4*)(sm + OFF_W2 + UN1 * G2))[i] = ((const float4*)U2w)[i];
    for (int i = tid; i < G1; i += THREADS) sm[OFF_B1 + i] = b1[i];
    for (int i = tid; i < G2; i += THREADS) sm[OFF_B2 + i] = b2[i];
    // zero both combined buffers
    for (int i = tid; i < 2 * ROWS * RSTRIDE; i += THREADS) sm[OFF_C + i] = 0.0f;

    __syncthreads();   // zeroing done before cp.async writes x

    // ---- thread mapping ----
    // warps 0-7: layer 1. 8-row tiles, K-split x2 across lane bit 4.
    // warps 8-15: layer 2. 4-row tiles, K-split x2, one step behind.
    const bool isL1 = (tid < 256);
    const int wg = (tid & 255) >> 5;   // 0..7 within layer group
    const int l  = tid & 31;
    const int kh = l >> 4;             // K-half (0/1)
    // L1: row base rg*8, unit pair up (0..31)
    const int rg = wg & 3;
    const int up = (l & 15) | ((wg >> 2) << 4);
    // L2: row base rg2*4, unit pair up2 (0..15)
    const int rg2 = wg;
    const int up2 = l & 15;

    float c1[4][2];   // L1: this thread's 4 activation rows (kh-half of 8)
    float c2[2][2];   // L2: 2 activation rows
#pragma unroll
    for (int r = 0; r < 4; r++) { c1[r][0] = c1[r][1] = 0.0f; }
#pragma unroll
    for (int r = 0; r < 2; r++) { c2[r][0] = c2[r][1] = 0.0f; }

    // ---- x prefetch: threads 0-255 move one float4/step into combined rows ----
    const int xrow = tid >> 3;   // 0..31 (valid for tid<256)
    const int xq   = tid & 7;
    const float* xg = x + ((size_t)(b0 + xrow) * T_STEPS) * NFEAT + xq * 4;
    uint32_t sx0 = (uint32_t)__cvta_generic_to_shared(sm + OFF_C + xrow * RSTRIDE + xq * 4);
    const uint32_t cbufbytes = ROWS * RSTRIDE * 4;   // 16384
    const bool xmover = (tid < 256);

    if (xmover) cp16(sx0, xg);    // x_0 -> buffer 0
    cp_commit();
    __syncthreads();

    // Iter t: L1 computes step t (t<T) reading buf rb=t&1, writing h1_t to wb.
    //         L2 computes step t-1 (t>=1) reading buf rb, writing h2_{t-1} to wb.
    for (int t = 0; t <= T_STEPS; ++t) {
        if (t < T_STEPS) cp_wait0();
        __syncthreads();
        if (t + 1 < T_STEPS && xmover)
            cp16(sx0 + ((t + 1) & 1) * cbufbytes, xg + (size_t)(t + 1) * NFEAT);
        cp_commit();
        const int rb = t & 1, wb = rb ^ 1;
        const float* cin  = sm + OFF_C + rb * (ROWS * RSTRIDE);
        float*       cout = sm + OFF_C + wb * (ROWS * RSTRIDE);

        if (isL1) {
            if (t < T_STEPS) {
                ull acc[8][4];
#pragma unroll
                for (int g = 0; g < 4; g++) {
                    ull bsv = (kh == 0) ? *(const ull*)(sm + OFF_B1 + g * UN1 + 2 * up) : 0ull;
#pragma unroll
                    for (int r = 0; r < 8; r++) acc[r][g] = bsv;
                }
                // gate cols = [x|h1] = cin cols 0..95; this thread: cols kh*48..+48
                panel48<8, G1, UN1>(acc,
                                    cin + rg * 8 * RSTRIDE + kh * 48,
                                    sm + OFF_W1 + (kh * 48) * G1 + 2 * up);
                // K-split reduction with partner lane (l ^ 16)
#pragma unroll
                for (int r = 0; r < 8; r++)
#pragma unroll
                    for (int g = 0; g < 4; g++)
                        acc[r][g] = add2(acc[r][g], __shfl_xor_sync(0xffffffffu, acc[r][g], 16));
                // activations: kh=0 -> rows 0..3, kh=1 -> rows 4..7 of the tile
#pragma unroll
                for (int r = 0; r < 4; r++) {
                    float2 zi = unpack2(kh ? acc[r + 4][0] : acc[r][0]);
                    float2 zf = unpack2(kh ? acc[r + 4][1] : acc[r][1]);
                    float2 zg = unpack2(kh ? acc[r + 4][2] : acc[r][2]);
                    float2 zo = unpack2(kh ? acc[r + 4][3] : acc[r][3]);
                    float i0 = sigm(zi.x), f0 = sigm(zf.x), g0 = tanh_(zg.x), o0 = sigm(zo.x);
                    float i1 = sigm(zi.y), f1 = sigm(zf.y), g1 = tanh_(zg.y), o1 = sigm(zo.y);
                    c1[r][0] = f0 * c1[r][0] + i0 * g0;
                    c1[r][1] = f1 * c1[r][1] + i1 * g1;
                    float2 h;
                    h.x = o0 * tanh_(c1[r][0]);
                    h.y = o1 * tanh_(c1[r][1]);
                    int row = rg * 8 + kh * 4 + r;
                    *(float2*)(cout + row * RSTRIDE + 32 + 2 * up) = h;
                }
            }
        } else {
            if (t >= 1) {
                ull acc2[4][4];
#pragma unroll
                for (int g = 0; g < 4; g++) {
                    ull bsv = (kh == 0) ? *(const ull*)(sm + OFF_B2 + g * UN2 + 2 * up2) : 0ull;
#pragma unroll
                    for (int r = 0; r < 4; r++) acc2[r][g] = bsv;
                }
                // gate cols = [h1|h2] = cin cols 32..127; this thread: cols 32+kh*48..+48
                panel48<4, G2, UN2>(acc2,
                                    cin + rg2 * 4 * RSTRIDE + 32 + kh * 48,
                                    sm + OFF_W2 + (kh * 48) * G2 + 2 * up2);
#pragma unroll
                for (int r = 0; r < 4; r++)
#pragma unroll
                    for (int g = 0; g < 4; g++)
                        acc2[r][g] = add2(acc2[r][g], __shfl_xor_sync(0xffffffffu, acc2[r][g], 16));
#pragma unroll
                for (int r = 0; r < 2; r++) {
                    float2 zi = unpack2(kh ? acc2[r + 2][0] : acc2[r][0]);
                    float2 zf = unpack2(kh ? acc2[r + 2][1] : acc2[r][1]);
                    float2 zg = unpack2(kh ? acc2[r + 2][2] : acc2[r][2]);
                    float2 zo = unpack2(kh ? acc2[r + 2][3] : acc2[r][3]);
                    float i0 = sigm(zi.x), f0 = sigm(zf.x), g0 = tanh_(zg.x), o0 = sigm(zo.x);
                    float i1 = sigm(zi.y), f1 = sigm(zf.y), g1 = tanh_(zg.y), o1 = sigm(zo.y);
                    c2[r][0] = f0 * c2[r][0] + i0 * g0;
                    c2[r][1] = f1 * c2[r][1] + i1 * g1;
                    float2 h;
                    h.x = o0 * tanh_(c2[r][0]);
                    h.y = o1 * tanh_(c2[r][1]);
                    int row = rg2 * 4 + kh * 2 + r;
                    *(float2*)(cout + row * RSTRIDE + 96 + 2 * up2) = h;
                }
            }
        }
    }
    __syncthreads();

    // final h2 = h2_{T-1}, written at iter t=T into buf ((T&1)^1), cols 96..127
    const float* h2f = sm + OFF_C + ((T_STEPS & 1) ^ 1) * (ROWS * RSTRIDE) + 96;

    // ================= head: MHA(seq=1) is identity-attention -> v@Wo, then MLP ===========
    // scratch lives in the (now dead) weight region
    float* sv  = sm + OFF_W1;            // 32x32
    float* so  = sm + OFF_W1 + 1024;     // 32x32
    float* sd1 = sm + OFF_W1 + 2048;     // 32x64
    for (int idx = tid; idx < ROWS * 32; idx += THREADS) {
        int r = idx >> 5, j = idx & 31;
        float s = bv[j];
        const float* h2row = h2f + r * RSTRIDE;
#pragma unroll
        for (int d = 0; d < 32; d++) s += h2row[d] * Wv[d * 32 + j];
        sv[idx] = s;
    }
    __syncthreads();
    for (int idx = tid; idx < ROWS * 32; idx += THREADS) {
        int r = idx >> 5, e = idx & 31;
        float s = bo[e];
#pragma unroll
        for (int j = 0; j < 32; j++) s += sv[r * 32 + j] * Wo[j * 32 + e];
        so[idx] = s;
    }
    __syncthreads();
    for (int idx = tid; idx < ROWS * 64; idx += THREADS) {
        int r = idx >> 6, m = idx & 63;
        float s = bd1[m];
#pragma unroll
        for (int e = 0; e < 32; e++) s += so[r * 32 + e] * Wd1[e * 64 + m];
        sd1[idx] = fmaxf(s, 0.0f);
    }
    __syncthreads();
    for (int idx = tid; idx < ROWS * 24; idx += THREADS) {
        int r = idx / 24, p = idx % 24;
        float s = bd2[p];
#pragma unroll
        for (int m = 0; m < 64; m++) s += sd1[r * 64 + m] * Wd2[m * 24 + p];
        out[(size_t)(b0 + r) * 24 + p] = s;
    }
}

extern "C" void kernel_launch(void* const* d_in, const int* in_sizes, int n_in,
                              void* d_out, int out_size) {
    const float* x   = (const float*)d_in[0];
    const float* W1  = (const float*)d_in[1];
    const float* U1w = (const float*)d_in[2];
    const float* b1  = (const float*)d_in[3];
    const float* W2  = (const float*)d_in[4];
    const float* U2w = (const float*)d_in[5];
    const float* b2  = (const float*)d_in[6];
    // d_in[7..10] = Wq, bq, Wk, bk: dead (softmax over seq-len 1 == 1)
    const float* Wv  = (const float*)d_in[11];
    const float* bv  = (const float*)d_in[12];
    const float* Wo  = (const float*)d_in[13];
    const float* bo  = (const float*)d_in[14];
    const float* Wd1 = (const float*)d_in[15];
    const float* bd1 = (const float*)d_in[16];
    const float* Wd2 = (const float*)d_in[17];
    const float* bd2 = (const float*)d_in[18];

    size_t smem = SMEM_FLOATS * sizeof(float);   // 181760 B
    cudaFuncSetAttribute(lstm_fused_kernel,
                         cudaFuncAttributeMaxDynamicSharedMemorySize, (int)smem);
    lstm_fused_kernel<<<CTAS, THREADS, smem>>>(
        x, W1, U1w, b1, W2, U2w, b2, Wv, bv, Wo, bo, Wd1, bd1, Wd2, bd2,
        (float*)d_out);
}